// round 5
// baseline (speedup 1.0000x reference)
#include <cuda_runtime.h>

#define NMAX  256
#define EDGES 2048
#define HDIM  64
#define EMBED 39
#define NT    256
#define XS    65          // padded row stride (conflict-free both directions)

struct Smem {
  float xsA[NMAX * XS];        // 66560 B
  float xsB[NMAX * XS];        // 66560 B
  float Ws[HDIM * HDIM];       // 16384 B
  unsigned int epack[EDGES];   // src | dst<<8 | valid<<16
  unsigned int esorted[EDGES]; // sorted by dst
  int   ofs[NMAX + 1];
  int   cursor[NMAX];
  float deg[NMAX];
  float dinv[NMAX];
  float skey[NMAX];
  int   sidx[NMAX];
  int   newid[NMAX];
  float rsum[2 * HDIM];
  float bvec[HDIM];
  float pvec[HDIM];
  float red[32];
};

template <int K>
__device__ __forceinline__ void gemm_rows(const float* __restrict__ cur,
                                          float* __restrict__ tmp,
                                          const float* __restrict__ Ws,
                                          int n, int tid) {
  if (tid < n) {
    float xr[K];
#pragma unroll
    for (int k = 0; k < K; ++k) xr[k] = cur[tid * XS + k];
    for (int j0 = 0; j0 < HDIM; j0 += 4) {
      float a0 = 0.f, a1 = 0.f, a2 = 0.f, a3 = 0.f;
#pragma unroll
      for (int k = 0; k < K; ++k) {
        const float4 w = *reinterpret_cast<const float4*>(&Ws[k * HDIM + j0]);
        a0 += xr[k] * w.x; a1 += xr[k] * w.y;
        a2 += xr[k] * w.z; a3 += xr[k] * w.w;
      }
      tmp[tid * XS + j0 + 0] = a0;
      tmp[tid * XS + j0 + 1] = a1;
      tmp[tid * XS + j0 + 2] = a2;
      tmp[tid * XS + j0 + 3] = a3;
    }
  }
}

__global__ __launch_bounds__(NT)
void gnn_kernel(const float* __restrict__ x,
                const int* __restrict__ ei,
                const float* __restrict__ W1, const float* __restrict__ b1, const float* __restrict__ p1,
                const float* __restrict__ W2, const float* __restrict__ b2, const float* __restrict__ p2,
                const float* __restrict__ W3, const float* __restrict__ b3, const float* __restrict__ p3,
                const float* __restrict__ lW1, const float* __restrict__ lb1,
                const float* __restrict__ lW2, const float* __restrict__ lb2,
                const float* __restrict__ lW3, const float* __restrict__ lb3,
                float* __restrict__ out) {
  extern __shared__ char smraw[];
  Smem& S = *reinterpret_cast<Smem*>(smraw);
  const int b    = blockIdx.x;
  const int tid  = threadIdx.x;
  const int lane = tid & 31;
  const int wid  = tid >> 5;

  // ---- load edges (int32, packed: node ids < 256 fit in u8) ----
  const int* eb = ei + (size_t)b * 2 * EDGES;
  for (int e = tid; e < EDGES; e += NT) {
    unsigned s = (unsigned)eb[e] & 255u;
    unsigned d = (unsigned)eb[EDGES + e] & 255u;
    S.epack[e] = s | (d << 8) | (1u << 16);
  }
  // ---- load x [256, 39] ----
  const float* xb = x + (size_t)b * NMAX * EMBED;
  for (int idx = tid; idx < NMAX * EMBED; idx += NT) {
    int r = idx / EMBED, c = idx - r * EMBED;
    S.xsA[r * XS + c] = xb[idx];
  }
  if (tid < 2 * HDIM) S.rsum[tid] = 0.f;

  float* cur = S.xsA;
  float* tmp = S.xsB;
  int n = NMAX;
  const int   kk[3] = {205, 164, 132};              // ceil(0.8*256), ceil(0.8*205), ceil(0.8*164)
  const float* Wl[3] = {W1, W2, W3};
  const float* bl[3] = {b1, b2, b3};
  const float* pl[3] = {p1, p2, p3};

  for (int layer = 0; layer < 3; ++layer) {
    const int K = (layer == 0) ? EMBED : HDIM;
    // ---- stage weights ----
    for (int idx = tid; idx < K * HDIM; idx += NT) S.Ws[idx] = Wl[layer][idx];
    if (tid < HDIM) { S.bvec[tid] = bl[layer][tid]; S.pvec[tid] = pl[layer][tid]; }
    for (int i = tid; i <= NMAX; i += NT) S.ofs[i] = 0;
    for (int i = tid; i < NMAX; i += NT) S.deg[i] = 1.0f;
    __syncthreads();

    // ---- GEMM: h = x @ W  (into tmp) ----
    if (layer == 0) gemm_rows<EMBED>(cur, tmp, S.Ws, n, tid);
    else            gemm_rows<HDIM>(cur, tmp, S.Ws, n, tid);

    // ---- degree + histogram by dst (disjoint from GEMM buffers) ----
    for (int e = tid; e < EDGES; e += NT) {
      unsigned u = S.epack[e];
      int d = (u >> 8) & 255;
      if (u >> 16) atomicAdd(&S.deg[d], 1.0f);
      atomicAdd(&S.ofs[d + 1], 1);
    }
    __syncthreads();
    for (int i = tid; i < NMAX; i += NT) S.dinv[i] = rsqrtf(S.deg[i]);
    // ---- Hillis-Steele inclusive scan over ofs[1..256] ----
    for (int off = 1; off < NMAX; off <<= 1) {
      int add = (tid >= off) ? S.ofs[1 + tid - off] : 0;
      __syncthreads();
      S.ofs[1 + tid] += add;
      __syncthreads();
    }
    for (int i = tid; i < NMAX; i += NT) S.cursor[i] = S.ofs[i];
    __syncthreads();
    // ---- scatter: counting-sorted edge list by dst ----
    for (int e = tid; e < EDGES; e += NT) {
      unsigned u = S.epack[e];
      int d = (u >> 8) & 255;
      int pos = atomicAdd(&S.cursor[d], 1);
      S.esorted[pos] = u;
    }
    __syncthreads();
    // ---- aggregation (warp per node, gather) -> cur, fused relu ----
    for (int i = wid; i < n; i += NT / 32) {
      float a0 = 0.f, a1 = 0.f;
      const int beg = S.ofs[i], end = S.ofs[i + 1];
      const float di = S.dinv[i];
      for (int p = beg; p < end; ++p) {
        unsigned u = S.esorted[p];
        int s = u & 255;
        float c = (u >> 16) ? S.dinv[s] : 0.f;
        a0 += c * tmp[s * XS + lane];
        a1 += c * tmp[s * XS + lane + 32];
      }
      const float idg = di * di;  // 1/deg
      float v0 = a0 * di + tmp[i * XS + lane]      * idg + S.bvec[lane];
      float v1 = a1 * di + tmp[i * XS + lane + 32] * idg + S.bvec[lane + 32];
      cur[i * XS + lane]      = fmaxf(v0, 0.f);
      cur[i * XS + lane + 32] = fmaxf(v1, 0.f);
    }
    __syncthreads();

    // ---- scores: tanh(x·p / ||p||) ----
    if (wid == 0) {
      float s2 = S.pvec[lane] * S.pvec[lane] + S.pvec[lane + 32] * S.pvec[lane + 32];
#pragma unroll
      for (int o = 16; o; o >>= 1) s2 += __shfl_xor_sync(0xffffffffu, s2, o);
      if (lane == 0) S.red[0] = 1.0f / sqrtf(s2);
    }
    __syncthreads();
    const float pscale = S.red[0];
    if (tid < n) {
      float s = 0.f;
#pragma unroll 8
      for (int j = 0; j < HDIM; ++j) s += cur[tid * XS + j] * S.pvec[j];
      S.skey[tid] = tanhf(s * pscale);
      S.sidx[tid] = tid;
    } else {
      S.skey[tid] = -1e30f;
      S.sidx[tid] = tid;
    }
    __syncthreads();
    // ---- bitonic sort 256: score desc, index asc on ties (lax.top_k stable) ----
    for (int ksz = 2; ksz <= NMAX; ksz <<= 1) {
      for (int j = ksz >> 1; j > 0; j >>= 1) {
        int i = tid, ixj = i ^ j;
        if (ixj > i) {
          float sa = S.skey[i], sb = S.skey[ixj];
          int   ia = S.sidx[i], ib = S.sidx[ixj];
          bool aFirst = (sa > sb) || (sa == sb && ia < ib);
          bool up = ((i & ksz) == 0);
          if (up ? !aFirst : aFirst) {
            S.skey[i] = sb; S.skey[ixj] = sa;
            S.sidx[i] = ib; S.sidx[ixj] = ia;
          }
        }
        __syncthreads();
      }
    }
    const int kcur = kk[layer];
    for (int i = tid; i < NMAX; i += NT) S.newid[i] = -1;
    __syncthreads();
    if (tid < kcur) S.newid[S.sidx[tid]] = tid;
    __syncthreads();
    // ---- pooled x -> tmp: rows ranked, scaled by score ----
    for (int r = wid; r < kcur; r += NT / 32) {
      int old = S.sidx[r];
      float v = S.skey[r];
      tmp[r * XS + lane]      = cur[old * XS + lane]      * v;
      tmp[r * XS + lane + 32] = cur[old * XS + lane + 32] * v;
    }
    // ---- remap edges with validity ----
    for (int e = tid; e < EDGES; e += NT) {
      unsigned u = S.epack[e];
      int s = u & 255, d = (u >> 8) & 255;
      int valid = (int)(u >> 16);
      int ns = S.newid[s], nd = S.newid[d];
      int nv = (valid && ns >= 0 && nd >= 0) ? 1 : 0;
      if (ns < 0) ns = 0;
      if (nd < 0) nd = 0;
      S.epack[e] = (unsigned)ns | ((unsigned)nd << 8) | ((unsigned)nv << 16);
    }
    __syncthreads();
    // ---- readout(pooled): concat(max, mean), accumulated ----
    if (tid < HDIM) {
      float m = -1e30f;
      for (int r = 0; r < kcur; ++r) m = fmaxf(m, tmp[r * XS + tid]);
      S.rsum[tid] += m;
    } else if (tid < 2 * HDIM) {
      int j = tid - HDIM;
      float s = 0.f;
      for (int r = 0; r < kcur; ++r) s += tmp[r * XS + j];
      S.rsum[HDIM + j] += s / (float)kcur;
    }
    // swap ping-pong
    float* t = cur; cur = tmp; tmp = t;
    n = kcur;
    __syncthreads();
  }

  // ---- MLP head: 128 -> 64 -> 32 -> 1, sigmoid ----
  if (tid < 64) {
    float a = lb1[tid];
#pragma unroll 8
    for (int i = 0; i < 128; ++i) a += S.rsum[i] * lW1[i * 64 + tid];
    S.skey[tid] = fmaxf(a, 0.f);   // reuse as h1
  }
  __syncthreads();
  if (tid < 32) {
    float a = lb2[tid];
#pragma unroll 8
    for (int j = 0; j < 64; ++j) a += S.skey[j] * lW2[j * 32 + tid];
    float h2 = fmaxf(a, 0.f);
    float v = h2 * lW3[tid];
#pragma unroll
    for (int o = 16; o; o >>= 1) v += __shfl_xor_sync(0xffffffffu, v, o);
    if (tid == 0) out[b] = 1.0f / (1.0f + expf(-(v + lb3[0])));
  }
}

extern "C" void kernel_launch(void* const* d_in, const int* in_sizes, int n_in,
                              void* d_out, int out_size) {
  const float* x   = (const float*)d_in[0];
  const int*   ei  = (const int*)d_in[1];
  const float* W1  = (const float*)d_in[2];
  const float* b1  = (const float*)d_in[3];
  const float* p1  = (const float*)d_in[4];
  const float* W2  = (const float*)d_in[5];
  const float* b2  = (const float*)d_in[6];
  const float* p2  = (const float*)d_in[7];
  const float* W3  = (const float*)d_in[8];
  const float* b3  = (const float*)d_in[9];
  const float* p3  = (const float*)d_in[10];
  const float* lW1 = (const float*)d_in[11];
  const float* lb1 = (const float*)d_in[12];
  const float* lW2 = (const float*)d_in[13];
  const float* lb2 = (const float*)d_in[14];
  const float* lW3 = (const float*)d_in[15];
  const float* lb3 = (const float*)d_in[16];
  float* out = (float*)d_out;

  const int B = in_sizes[0] / (NMAX * EMBED);
  const size_t sm = sizeof(Smem);
  cudaFuncSetAttribute(gnn_kernel, cudaFuncAttributeMaxDynamicSharedMemorySize, (int)sm);
  gnn_kernel<<<B, NT, sm>>>(x, ei, W1, b1, p1, W2, b2, p2, W3, b3, p3,
                            lW1, lb1, lW2, lb2, lW3, lb3, out);
}

// round 6
// speedup vs baseline: 1.1682x; 1.1682x over previous
#include <cuda_runtime.h>

#define NMAX  256
#define EDGES 2048
#define HDIM  64
#define EMBED 39
#define NT    512
#define XS    66          // even stride: 8B-aligned u64 lane pairs, conflict-free

#define FMA_F32X2(d, a, b, c) \
  asm("fma.rn.f32x2 %0, %1, %2, %3;" : "=l"(d) : "l"(a), "l"(b), "l"(c))

// interleaved column mapping: col c -> word offset within row
__device__ __forceinline__ int cmap(int c) { return ((c & 31) << 1) | (c >> 5); }

struct Smem {
  float xsA[NMAX * XS];            // 67584 B
  float xsB[NMAX * XS];            // 67584 B
  float Ws[HDIM * HDIM];           // 16384 B
  unsigned int epack[EDGES];       // src | dst<<8 | valid<<16
  unsigned int esorted[EDGES];     // valid edges sorted by dst (src only)
  unsigned long long skey64[NMAX]; // packed sort keys
  int   hist[NMAX];
  int   ofs[NMAX + 1];
  int   cursor[NMAX];
  float dinv[NMAX];
  int   newid[NMAX];
  float rsum[2 * HDIM];
  float bvec[HDIM];
  float pvec[HDIM];
  float h1[HDIM];
  int   wsum[16];
  float red[4];
};

__device__ __forceinline__ unsigned long long make_key(float s, int idx) {
  unsigned bits = __float_as_uint(s);
  unsigned m = (bits & 0x80000000u) ? ~bits : (bits | 0x80000000u); // asc map
  unsigned hi = ~m;                                                // desc
  return ((unsigned long long)hi << 32) | (unsigned)idx;
}
__device__ __forceinline__ float key_score(unsigned long long k) {
  unsigned m = ~(unsigned)(k >> 32);
  unsigned bits = (m & 0x80000000u) ? (m ^ 0x80000000u) : ~m;
  return __uint_as_float(bits);
}

__device__ __forceinline__ unsigned long long ce_shfl(unsigned long long k, int j, bool takeMin) {
  unsigned long long o = __shfl_xor_sync(0xffffffffu, k, j);
  unsigned long long mn = (o < k) ? o : k;
  unsigned long long mx = (o < k) ? k : o;
  return takeMin ? mn : mx;
}

__device__ __forceinline__ void smem_ce(unsigned long long* a, int tid, int j, int ksz) {
  if (tid < 128) {
    int low = tid & (j - 1);
    int i = ((tid ^ low) << 1) | low;
    int p = i | j;
    unsigned long long x = a[i], y = a[p];
    bool asc = ((i & ksz) == 0);
    bool sw = asc ? (x > y) : (x < y);
    if (sw) { a[i] = y; a[p] = x; }
  }
}

template <int K, bool ILV>
__device__ __forceinline__ void gemm512(const float* __restrict__ cur,
                                        float* __restrict__ tmp,
                                        const float* __restrict__ Ws,
                                        int n, int tid) {
  const int row  = tid >> 1;
  const int hbit = tid & 1;
  const int half = hbit << 5;
  if (row >= n) return;
  unsigned long long acc[16];
#pragma unroll
  for (int i = 0; i < 16; ++i) acc[i] = 0ull;
#pragma unroll 4
  for (int k = 0; k < K; ++k) {
    float xv = cur[row * XS + (ILV ? (((k & 31) << 1) | (k >> 5)) : k)];
    unsigned long long xp;
    asm("mov.b64 %0, {%1, %1};" : "=l"(xp) : "r"(__float_as_uint(xv)));
#pragma unroll
    for (int j0 = 0; j0 < 8; ++j0) {
      const ulonglong2 w2 = *reinterpret_cast<const ulonglong2*>(&Ws[k * HDIM + half + j0 * 4]);
      FMA_F32X2(acc[j0 * 2],     xp, w2.x, acc[j0 * 2]);
      FMA_F32X2(acc[j0 * 2 + 1], xp, w2.y, acc[j0 * 2 + 1]);
    }
  }
#pragma unroll
  for (int j0 = 0; j0 < 8; ++j0) {
#pragma unroll
    for (int t = 0; t < 2; ++t) {
      unsigned lo, hi;
      asm("mov.b64 {%0, %1}, %2;" : "=r"(lo), "=r"(hi) : "l"(acc[j0 * 2 + t]));
      int c0 = j0 * 4 + t * 2;  // col within half (0..31), maps to c0*2 + hbit
      tmp[row * XS + c0 * 2 + hbit]       = __uint_as_float(lo);
      tmp[row * XS + (c0 + 1) * 2 + hbit] = __uint_as_float(hi);
    }
  }
}

__global__ __launch_bounds__(NT)
void gnn_kernel(const float* __restrict__ x,
                const int* __restrict__ ei,
                const float* __restrict__ W1, const float* __restrict__ b1, const float* __restrict__ p1,
                const float* __restrict__ W2, const float* __restrict__ b2, const float* __restrict__ p2,
                const float* __restrict__ W3, const float* __restrict__ b3, const float* __restrict__ p3,
                const float* __restrict__ lW1, const float* __restrict__ lb1,
                const float* __restrict__ lW2, const float* __restrict__ lb2,
                const float* __restrict__ lW3, const float* __restrict__ lb3,
                float* __restrict__ out) {
  extern __shared__ char smraw[];
  Smem& S = *reinterpret_cast<Smem*>(smraw);
  const int b    = blockIdx.x;
  const int tid  = threadIdx.x;
  const int lane = tid & 31;
  const int wid  = tid >> 5;

  // ---- load edges (int32) ----
  const int* eb = ei + (size_t)b * 2 * EDGES;
#pragma unroll
  for (int e = tid; e < EDGES; e += NT) {
    unsigned s = (unsigned)eb[e] & 255u;
    unsigned d = (unsigned)eb[EDGES + e] & 255u;
    S.epack[e] = s | (d << 8) | (1u << 16);
  }
  // ---- load x [256, 39] (linear layout) ----
  const float* xb = x + (size_t)b * NMAX * EMBED;
  for (int idx = tid; idx < NMAX * EMBED; idx += NT) {
    int r = idx / EMBED, c = idx - r * EMBED;
    S.xsA[r * XS + c] = xb[idx];
  }
  if (tid < 2 * HDIM) S.rsum[tid] = 0.f;

  float* cur = S.xsA;
  float* tmp = S.xsB;
  int n = NMAX;
  const int kk[3] = {205, 164, 132};
  const float* Wl[3] = {W1, W2, W3};
  const float* bl[3] = {b1, b2, b3};
  const float* pl[3] = {p1, p2, p3};

  for (int layer = 0; layer < 3; ++layer) {
    const int KD = (layer == 0) ? EMBED : HDIM;
    // ---- stage ----
    for (int idx = tid; idx < KD * HDIM; idx += NT) S.Ws[idx] = Wl[layer][idx];
    if (tid >= 64 && tid < 128) { int j = tid - 64; S.bvec[j] = bl[layer][j]; S.pvec[j] = pl[layer][j]; }
    if (tid >= 128 && tid < 384) S.hist[tid - 128] = 0;
    if (tid < 32) {  // pscale = 1/||p||
      float a = pl[layer][lane], c2 = pl[layer][lane + 32];
      float s2 = a * a + c2 * c2;
#pragma unroll
      for (int o = 16; o; o >>= 1) s2 += __shfl_xor_sync(0xffffffffu, s2, o);
      if (lane == 0) S.red[0] = rsqrtf(s2);
    }
    __syncthreads();

    // ---- GEMM: tmp = cur @ W (interleaved output) ----
    if (layer == 0) gemm512<EMBED, false>(cur, tmp, S.Ws, n, tid);
    else            gemm512<HDIM,  true >(cur, tmp, S.Ws, n, tid);

    // ---- histogram of VALID edges by dst ----
#pragma unroll
    for (int e = tid; e < EDGES; e += NT) {
      unsigned u = S.epack[e];
      if (u >> 16) atomicAdd(&S.hist[(u >> 8) & 255], 1);
    }
    __syncthreads();

    // ---- warp scan -> ofs / cursor / dinv ----
    int myc = 0, mys = 0;
    const int myw = tid >> 5;
    if (tid < NMAX) {
      myc = S.hist[tid];
      mys = myc;
#pragma unroll
      for (int o = 1; o < 32; o <<= 1) {
        int t = __shfl_up_sync(0xffffffffu, mys, o);
        if (lane >= o) mys += t;
      }
      if (lane == 31) S.wsum[myw] = mys;
    }
    __syncthreads();
    if (tid < 32) {
      int v = (tid < 8) ? S.wsum[tid] : 0;
#pragma unroll
      for (int o = 1; o < 8; o <<= 1) {
        int t = __shfl_up_sync(0xffffffffu, v, o);
        if (lane >= o) v += t;
      }
      if (tid < 8) S.wsum[tid] = v;  // inclusive warp totals
    }
    __syncthreads();
    if (tid < NMAX) {
      int base = myw ? S.wsum[myw - 1] : 0;
      int incl = mys + base;
      S.ofs[tid + 1] = incl;
      S.cursor[tid]  = incl - myc;
      S.dinv[tid]    = rsqrtf(1.0f + (float)myc);
      if (tid == 0) S.ofs[0] = 0;
    }
    __syncthreads();

    // ---- scatter valid edges (src only) sorted by dst ----
#pragma unroll
    for (int e = tid; e < EDGES; e += NT) {
      unsigned u = S.epack[e];
      if (u >> 16) {
        int d = (u >> 8) & 255;
        int pos = atomicAdd(&S.cursor[d], 1);
        S.esorted[pos] = u & 255u;
      }
    }
    __syncthreads();

    // ---- aggregation (warp/node) + relu + fused score -> cur, skey64 ----
    const float pscale = S.red[0];
    for (int i = wid; i < n; i += NT / 32) {
      const int beg = S.ofs[i], end = S.ofs[i + 1];
      const float di = S.dinv[i];
      unsigned long long acc = 0ull;
      for (int p = beg; p < end; ++p) {
        int sN = S.esorted[p];
        float c = S.dinv[sN];
        unsigned long long cp, hv;
        asm("mov.b64 %0, {%1, %1};" : "=l"(cp) : "r"(__float_as_uint(c)));
        hv = *reinterpret_cast<const unsigned long long*>(&tmp[sN * XS + (lane << 1)]);
        FMA_F32X2(acc, cp, hv, acc);
      }
      unsigned a0u, a1u;
      asm("mov.b64 {%0, %1}, %2;" : "=r"(a0u), "=r"(a1u) : "l"(acc));
      const float2 hself = *reinterpret_cast<const float2*>(&tmp[i * XS + (lane << 1)]);
      const float idg = di * di;
      float v0 = fmaxf(__uint_as_float(a0u) * di + hself.x * idg + S.bvec[lane], 0.f);
      float v1 = fmaxf(__uint_as_float(a1u) * di + hself.y * idg + S.bvec[lane + 32], 0.f);
      cur[i * XS + (lane << 1)]     = v0;
      cur[i * XS + (lane << 1) + 1] = v1;
      float sc = v0 * S.pvec[lane] + v1 * S.pvec[lane + 32];
#pragma unroll
      for (int o = 16; o; o >>= 1) sc += __shfl_xor_sync(0xffffffffu, sc, o);
      if (lane == 0) S.skey64[i] = make_key(tanhf(sc * pscale), i);
    }
    // sentinels + newid init (disjoint addresses)
    for (int i = n + tid; i < NMAX; i += NT) S.skey64[i] = make_key(-1e30f, i);
    if (tid < NMAX) S.newid[tid] = -1;
    __syncthreads();

    // ---- bitonic sort 256 u64 keys (hybrid shuffle/smem) ----
    if (tid < NMAX) {
      unsigned long long k = S.skey64[tid];
#pragma unroll
      for (int ksz = 2; ksz <= 32; ksz <<= 1)
#pragma unroll
        for (int j = ksz >> 1; j > 0; j >>= 1)
          k = ce_shfl(k, j, ((tid & j) == 0) == ((tid & ksz) == 0));
      S.skey64[tid] = k;
    }
    __syncthreads();
#pragma unroll
    for (int ksz = 64; ksz <= 256; ksz <<= 1) {
      for (int j = ksz >> 1; j >= 32; j >>= 1) {
        smem_ce(S.skey64, tid, j, ksz);
        __syncthreads();
      }
      if (tid < NMAX) {
        unsigned long long k = S.skey64[tid];
        const bool asc = ((tid & ksz) == 0);
#pragma unroll
        for (int j = 16; j > 0; j >>= 1)
          k = ce_shfl(k, j, ((tid & j) == 0) == asc);
        S.skey64[tid] = k;
      }
      __syncthreads();
    }

    const int kcur = kk[layer];
    if (tid < kcur) {
      int old = (int)(S.skey64[tid] & 0xffffffffull);
      S.newid[old] = tid;
    }
    __syncthreads();

    // ---- pooled rows -> tmp (scaled); remap edges ----
    for (int r = wid; r < kcur; r += NT / 32) {
      unsigned long long key = S.skey64[r];
      int old = (int)(key & 0xffffffffull);
      float v = key_score(key);
      float2 h2 = *reinterpret_cast<const float2*>(&cur[old * XS + (lane << 1)]);
      tmp[r * XS + (lane << 1)]     = h2.x * v;
      tmp[r * XS + (lane << 1) + 1] = h2.y * v;
    }
    if (layer < 2) {
#pragma unroll
      for (int e = tid; e < EDGES; e += NT) {
        unsigned u = S.epack[e];
        int sN = u & 255, d = (u >> 8) & 255;
        int valid = (int)(u >> 16);
        int ns = S.newid[sN], nd = S.newid[d];
        int nv = (valid && ns >= 0 && nd >= 0) ? 1 : 0;
        if (ns < 0) ns = 0;
        if (nd < 0) nd = 0;
        S.epack[e] = (unsigned)ns | ((unsigned)nd << 8) | ((unsigned)nv << 16);
      }
    }
    __syncthreads();

    // ---- readout: warp per column group ----
    for (int c = wid; c < HDIM; c += NT / 32) {
      const int off = cmap(c);
      float m = -1e30f, sm = 0.f;
      for (int r = lane; r < kcur; r += 32) {
        float v = tmp[r * XS + off];
        m = fmaxf(m, v);
        sm += v;
      }
#pragma unroll
      for (int o = 16; o; o >>= 1) {
        m  = fmaxf(m, __shfl_xor_sync(0xffffffffu, m, o));
        sm += __shfl_xor_sync(0xffffffffu, sm, o);
      }
      if (lane == 0) {
        S.rsum[c]        += m;
        S.rsum[HDIM + c] += sm / (float)kcur;
      }
    }
    float* t = cur; cur = tmp; tmp = t;
    n = kcur;
    __syncthreads();
  }

  // ---- MLP head: 128 -> 64 -> 32 -> 1, sigmoid ----
  if (tid < 64) {
    float a = lb1[tid];
#pragma unroll 8
    for (int i = 0; i < 128; ++i) a += S.rsum[i] * lW1[i * 64 + tid];
    S.h1[tid] = fmaxf(a, 0.f);
  }
  __syncthreads();
  if (tid < 32) {
    float a = lb2[tid];
#pragma unroll 8
    for (int j = 0; j < 64; ++j) a += S.h1[j] * lW2[j * 32 + tid];
    float h2 = fmaxf(a, 0.f);
    float v = h2 * lW3[tid];
#pragma unroll
    for (int o = 16; o; o >>= 1) v += __shfl_xor_sync(0xffffffffu, v, o);
    if (tid == 0) out[b] = 1.0f / (1.0f + expf(-(v + lb3[0])));
  }
}

extern "C" void kernel_launch(void* const* d_in, const int* in_sizes, int n_in,
                              void* d_out, int out_size) {
  const float* x   = (const float*)d_in[0];
  const int*   ei  = (const int*)d_in[1];
  const float* W1  = (const float*)d_in[2];
  const float* b1  = (const float*)d_in[3];
  const float* p1  = (const float*)d_in[4];
  const float* W2  = (const float*)d_in[5];
  const float* b2  = (const float*)d_in[6];
  const float* p2  = (const float*)d_in[7];
  const float* W3  = (const float*)d_in[8];
  const float* b3  = (const float*)d_in[9];
  const float* p3  = (const float*)d_in[10];
  const float* lW1 = (const float*)d_in[11];
  const float* lb1 = (const float*)d_in[12];
  const float* lW2 = (const float*)d_in[13];
  const float* lb2 = (const float*)d_in[14];
  const float* lW3 = (const float*)d_in[15];
  const float* lb3 = (const float*)d_in[16];
  float* out = (float*)d_out;

  const int B = in_sizes[0] / (NMAX * EMBED);
  const size_t sm = sizeof(Smem);
  cudaFuncSetAttribute(gnn_kernel, cudaFuncAttributeMaxDynamicSharedMemorySize, (int)sm);
  gnn_kernel<<<B, NT, sm>>>(x, ei, W1, b1, p1, W2, b2, p2, W3, b3, p3,
                            lW1, lb1, lW2, lb2, lW3, lb3, out);
}